// round 1
// baseline (speedup 1.0000x reference)
#include <cuda_runtime.h>
#include <cfloat>

// Problem constants
#define C_DIM   256
#define D_DICT  1024
#define HW_DIM  1024      // 32*32
#define N_IMG   32
#define T_PER   (N_IMG * HW_DIM)   // 32768 positions per input

// Tiling
#define BM 64      // positions per block
#define BN 128     // dict rows per j-tile
#define BK 64      // k tile
#define TM 4
#define TN 8
#define NTHREADS 256   // 16x16

#define DS_STRIDE 132  // BN + 4 pad (16B aligned rows)

// Shared layout (floats):
//  xs   [0, 16384)        : x tile [256][64]
//  ds   [16384, 24832)    : dict tile [64][132]
//  xn   [24832, 24896)    : x row norms [64]
//  bidx [24896, 24960)    : best index per row (int)
// reduction rv/ri reuse ds region; drows (64x257) reuses [0, 16448)
#define SM_FLOATS 24960
#define SM_BYTES  (SM_FLOATS * 4)

__device__ float g_dnorm[D_DICT];

__global__ void dnorm_kernel(const float* __restrict__ dict) {
    int row  = blockIdx.x * 8 + (threadIdx.x >> 5);
    int lane = threadIdx.x & 31;
    const float* dp = dict + (size_t)row * C_DIM;
    float s = 0.f;
    #pragma unroll
    for (int i = lane; i < C_DIM; i += 32) { float v = dp[i]; s += v * v; }
    #pragma unroll
    for (int o = 16; o; o >>= 1) s += __shfl_xor_sync(0xffffffffu, s, o);
    if (lane == 0) g_dnorm[row] = s;
}

__global__ __launch_bounds__(NTHREADS) void vq_main(
    const float* __restrict__ x0,
    const float* __restrict__ x1,
    const float* __restrict__ dict,
    float* __restrict__ out)
{
    extern __shared__ float smem[];
    float* xs = smem;                  // [256][64]
    float* ds = smem + 16384;          // [64][132]
    float* xn = smem + 24832;          // [64]
    int*   bidx_s = (int*)(smem + 24896); // [64]
    // aliases (phase-separated by __syncthreads)
    float* rv = ds;                    // [64][16]
    int*   ri = (int*)(ds + 1024);     // [64][16]
    float* drows = smem;               // [64][257]

    const int tid = threadIdx.x;
    const int tx = tid & 15;           // col group
    const int ty = tid >> 4;           // row group

    const int which = blockIdx.y;
    const float* x = which ? x1 : x0;
    const size_t obase = which ? (size_t)16809984 : 0;
    float* emb    = out + obase;                       // [32][256][1024]
    float* embpt  = out + obase + 8388608;
    float* idxout = out + obase + 16777216;            // [32768]

    const int t0  = blockIdx.x * BM;                   // global position base
    const int n   = t0 >> 10;                          // image
    const int hw0 = t0 & 1023;
    const float* xb = x + (size_t)n * C_DIM * HW_DIM + hw0;

    // ---- load x tile: xs[c][m], coalesced float4 along m ----
    #pragma unroll
    for (int it = 0; it < 16; ++it) {
        int idx = it * NTHREADS + tid;        // 0..4095 float4 units
        int c   = idx >> 4;                   // 0..255
        int m4  = (idx & 15) << 2;            // 0..60
        *(float4*)&xs[c * 64 + m4] = *(const float4*)&xb[(size_t)c * HW_DIM + m4];
    }
    __syncthreads();

    // ---- x norms ----
    if (tid < 64) {
        float s = 0.f;
        #pragma unroll 8
        for (int c = 0; c < C_DIM; ++c) { float v = xs[c * 64 + tid]; s += v * v; }
        xn[tid] = s;
    }
    __syncthreads();

    float xnr[TM];
    #pragma unroll
    for (int i = 0; i < TM; ++i) xnr[i] = xn[ty * TM + i];

    float bv[TM];
    int   bi[TM];
    #pragma unroll
    for (int i = 0; i < TM; ++i) { bv[i] = FLT_MAX; bi[i] = 0; }

    // ---- main loop over dict tiles ----
    for (int j0 = 0; j0 < D_DICT; j0 += BN) {
        float acc[TM][TN];
        #pragma unroll
        for (int i = 0; i < TM; ++i)
            #pragma unroll
            for (int l = 0; l < TN; ++l) acc[i][l] = 0.f;

        for (int k0 = 0; k0 < C_DIM; k0 += BK) {
            __syncthreads();   // previous ds consumers done
            // fill ds[kk][jj] (transposed store)
            #pragma unroll
            for (int r = 0; r < 8; ++r) {
                int idx = r * NTHREADS + tid;       // 0..2047 float4 units
                int jj  = idx >> 4;                 // 0..127
                int kk4 = (idx & 15) << 2;          // 0..60
                float4 v = *(const float4*)&dict[(size_t)(j0 + jj) * C_DIM + k0 + kk4];
                ds[(kk4 + 0) * DS_STRIDE + jj] = v.x;
                ds[(kk4 + 1) * DS_STRIDE + jj] = v.y;
                ds[(kk4 + 2) * DS_STRIDE + jj] = v.z;
                ds[(kk4 + 3) * DS_STRIDE + jj] = v.w;
            }
            __syncthreads();

            #pragma unroll 16
            for (int kk = 0; kk < BK; ++kk) {
                float4 a  = *(float4*)&xs[(k0 + kk) * 64 + (ty << 2)];
                float4 b0 = *(float4*)&ds[kk * DS_STRIDE + (tx << 3)];
                float4 b1 = *(float4*)&ds[kk * DS_STRIDE + (tx << 3) + 4];
                float av[TM] = {a.x, a.y, a.z, a.w};
                float bw[TN] = {b0.x, b0.y, b0.z, b0.w, b1.x, b1.y, b1.z, b1.w};
                #pragma unroll
                for (int i = 0; i < TM; ++i)
                    #pragma unroll
                    for (int l = 0; l < TN; ++l)
                        acc[i][l] += av[i] * bw[l];
            }
        }

        // distances + running argmin (ascending j => strict < keeps first min)
        const float* dnp = &g_dnorm[j0 + (tx << 3)];
        float dn[TN];
        #pragma unroll
        for (int l = 0; l < TN; ++l) dn[l] = dnp[l];
        #pragma unroll
        for (int i = 0; i < TM; ++i) {
            #pragma unroll
            for (int l = 0; l < TN; ++l) {
                float v = -2.0f * acc[i][l] + dn[l] + xnr[i];
                int j = j0 + (tx << 3) + l;
                if (v < bv[i]) { bv[i] = v; bi[i] = j; }
            }
        }
    }

    // ---- cross-thread argmin reduction (with index tie-break) ----
    __syncthreads();
    #pragma unroll
    for (int i = 0; i < TM; ++i) {
        int m = ty * TM + i;
        rv[m * 16 + tx] = bv[i];
        ri[m * 16 + tx] = bi[i];
    }
    __syncthreads();
    if (tid < 64) {
        float best = rv[tid * 16];
        int   bj   = ri[tid * 16];
        #pragma unroll
        for (int t = 1; t < 16; ++t) {
            float v = rv[tid * 16 + t];
            int   j = ri[tid * 16 + t];
            if (v < best || (v == best && j < bj)) { best = v; bj = j; }
        }
        bidx_s[tid] = bj;
        idxout[t0 + tid] = (float)bj;
    }
    __syncthreads();

    // ---- gather chosen dict rows into smem (coalesced), then write outputs ----
    #pragma unroll 4
    for (int m = 0; m < BM; ++m) {
        drows[m * 257 + tid] = dict[(size_t)bidx_s[m] * C_DIM + tid];
    }
    __syncthreads();

    float* eb  = emb   + (size_t)n * C_DIM * HW_DIM + hw0;
    float* ebp = embpt + (size_t)n * C_DIM * HW_DIM + hw0;
    #pragma unroll 4
    for (int it = 0; it < 64; ++it) {
        int lin = it * NTHREADS + tid;     // 0..16383
        int m = lin & 63;
        int c = lin >> 6;
        float v = drows[m * 257 + c];
        size_t o = (size_t)c * HW_DIM + m;
        eb[o]  = v;
        ebp[o] = v;
    }
}

extern "C" void kernel_launch(void* const* d_in, const int* in_sizes, int n_in,
                              void* d_out, int out_size) {
    const float* x0   = (const float*)d_in[0];
    const float* x1   = (const float*)d_in[1];
    const float* dict = (const float*)d_in[2];
    float* out = (float*)d_out;

    cudaFuncSetAttribute(vq_main, cudaFuncAttributeMaxDynamicSharedMemorySize, SM_BYTES);

    dnorm_kernel<<<128, 256>>>(dict);
    dim3 grid(T_PER / BM, 2);
    vq_main<<<grid, NTHREADS, SM_BYTES>>>(x0, x1, dict, out);
}